// round 1
// baseline (speedup 1.0000x reference)
#include <cuda_runtime.h>

#define CC   48
#define C3   144
#define HH   56
#define WW   56
#define HW   3136          // 56*56
#define NR   9216          // 64 * 144 rows of yf
#define DD   49
#define DP   64            // padded row stride
#define BM   64            // queries per CTA
#define BN   128           // keys per tile
#define PTS  68            // Pt shared stride (floats)

// smem floats: Qt 49*64 + Kt 49*128 + Kr 128*64 + Pt 128*68 + den 64
#define ATTN_SMEM_FLOATS (DD*BM + DD*BN + BN*DP + BN*PTS + BM)
#define ATTN_SMEM_BYTES  (ATTN_SMEM_FLOATS * 4)

// scratch (device globals: allocation-free per harness rules)
__device__ float g_yf_rm[NR * DP];   // yf row-major, cols 49..63 stay zero
__device__ float g_yf_t[DD * NR];    // yf transposed [k][row]
__device__ float g_yhat[NR * DP];    // attention output rows

// ---------------------------------------------------------------------------
// Kernel A: three depthwise convs -> yf in two layouts.
// Forward "window" index is the FLAT reshape: g = lin/49, p = lin%49.
// ---------------------------------------------------------------------------
__global__ void conv_kernel(const float* __restrict__ x,
                            const float* __restrict__ w3,
                            const float* __restrict__ w5,
                            const float* __restrict__ w7) {
    int idx = blockIdx.x * blockDim.x + threadIdx.x;
    if (idx >= C3 * HW) return;
    int c3  = idx / HW;
    int rem = idx - c3 * HW;
    int h = rem / WW;
    int w = rem - h * WW;
    int b = c3 / CC;          // 0:3x3  1:5x5  2:7x7
    int c = c3 - b * CC;
    int R = b + 1;
    int ks = 2 * R + 1;
    const float* wp = (b == 0 ? w3 : (b == 1 ? w5 : w7)) + c * ks * ks;
    const float* xc = x + c * HW;
    float sum = 0.f;
    #pragma unroll 1
    for (int dh = -R; dh <= R; dh++) {
        int hh = h + dh;
        if (hh < 0 || hh >= HH) continue;
        const float* xr = xc + hh * WW;
        const float* wr = wp + (dh + R) * ks + R;
        #pragma unroll 1
        for (int dw = -R; dw <= R; dw++) {
            int ww = w + dw;
            if (ww < 0 || ww >= WW) continue;
            sum += xr[ww] * wr[dw];
        }
    }
    int lin = h * WW + w;
    int g = lin / DD;
    int p = lin - g * DD;
    int r = g * C3 + c3;
    g_yf_rm[r * DP + p]  = sum;
    g_yf_t[p * NR + r]   = sum;
}

// ---------------------------------------------------------------------------
// Kernel B: flash-style attention, no max-subtraction (exponent bounded).
// O[64 x 64pad] accumulated in registers; denominator = GEMM column 49
// via a ones-column appended to the V tile.
// ---------------------------------------------------------------------------
__global__ void __launch_bounds__(256, 1) attn_kernel() {
    extern __shared__ float smem[];
    float* Qt  = smem;                       // [49][64]
    float* Kt  = Qt + DD * BM;               // [49][128]
    float* Kr  = Kt + DD * BN;               // [128][64] (col 49 := 1.0)
    float* Pt  = Kr + BN * DP;               // [128][PTS]
    float* dsh = Pt + BN * PTS;              // [64]

    const int tid = threadIdx.x;
    const int q0  = blockIdx.x * BM;

    // S-phase mapping: rows 4*tm..+3, cols tn + 16*j (j<8)
    const int tn = tid & 15;
    const int tm = tid >> 4;
    // PV-phase mapping: rows 4*tm..+3, cols 4*tn..+3  (same tn/tm reuse)

    // load Q tile (transposed layout -> conflict-free)
    for (int i = tid; i < DD * BM; i += 256) {
        int k = i >> 6, m = i & 63;
        Qt[i] = g_yf_t[k * NR + q0 + m];
    }

    float o[4][4] = {};
    const float CEXP = 0.029442755936583f;   // log2(e) / 49

    for (int n0 = 0; n0 < NR; n0 += BN) {
        __syncthreads();
        // K tile transposed for S GEMM
        for (int i = tid; i < DD * BN; i += 256) {
            int k = i >> 7, n = i & 127;
            Kt[i] = g_yf_t[k * NR + n0 + n];
        }
        // K tile row-major for PV GEMM; col 49 = 1.0 (denominator column),
        // cols 50..63 forced to 0 (no reliance on global padding)
        for (int i = tid; i < BN * DP; i += 256) {
            int d = i & 63;
            float v = g_yf_rm[n0 * DP + i];
            Kr[i] = (d < DD) ? v : (d == DD ? 1.0f : 0.0f);
        }
        __syncthreads();

        // ---- S = Q K^T ----
        float s[4][8] = {};
        #pragma unroll 7
        for (int k = 0; k < DD; k++) {
            float4 q4 = *(const float4*)(Qt + k * BM + 4 * tm);
            const float* krow = Kt + k * BN + tn;
            #pragma unroll
            for (int j = 0; j < 8; j++) {
                float kv = krow[16 * j];
                s[0][j] += q4.x * kv;
                s[1][j] += q4.y * kv;
                s[2][j] += q4.z * kv;
                s[3][j] += q4.w * kv;
            }
        }
        // ---- P = exp(S/49), store transposed to shared ----
        #pragma unroll
        for (int j = 0; j < 8; j++) {
            int n = tn + 16 * j;
            float4 pv;
            pv.x = exp2f(s[0][j] * CEXP);
            pv.y = exp2f(s[1][j] * CEXP);
            pv.z = exp2f(s[2][j] * CEXP);
            pv.w = exp2f(s[3][j] * CEXP);
            *(float4*)(Pt + n * PTS + 4 * tm) = pv;
        }
        __syncthreads();

        // ---- O += P V  (V = K tile, plus ones column) ----
        #pragma unroll 4
        for (int n = 0; n < BN; n++) {
            float4 p4 = *(const float4*)(Pt + n * PTS + 4 * tm);
            float4 k4 = *(const float4*)(Kr + n * DP + 4 * tn);
            o[0][0] += p4.x * k4.x; o[0][1] += p4.x * k4.y; o[0][2] += p4.x * k4.z; o[0][3] += p4.x * k4.w;
            o[1][0] += p4.y * k4.x; o[1][1] += p4.y * k4.y; o[1][2] += p4.y * k4.z; o[1][3] += p4.y * k4.w;
            o[2][0] += p4.z * k4.x; o[2][1] += p4.z * k4.y; o[2][2] += p4.z * k4.z; o[2][3] += p4.z * k4.w;
            o[3][0] += p4.w * k4.x; o[3][1] += p4.w * k4.y; o[3][2] += p4.w * k4.z; o[3][3] += p4.w * k4.w;
        }
    }

    // denominator lives in column 49 -> owned by tn==12 (cols 48..51, j==1)
    __syncthreads();
    if (tn == 12) {
        #pragma unroll
        for (int i = 0; i < 4; i++) dsh[4 * tm + i] = o[i][1];
    }
    __syncthreads();
    #pragma unroll
    for (int i = 0; i < 4; i++) {
        float rd = 1.0f / dsh[4 * tm + i];
        float4 v = make_float4(o[i][0] * rd, o[i][1] * rd, o[i][2] * rd, o[i][3] * rd);
        *(float4*)(g_yhat + (q0 + 4 * tm + i) * DP + 4 * tn) = v;
    }
}

// ---------------------------------------------------------------------------
// Kernel C: pointwise conv + bias + residual. One CTA per true 7x7 window.
// Inverse mapping uses SPATIAL windows: r = ((h/7)*8 + w/7)*144 + i,
// p = (h%7)*7 + (w%7).
// ---------------------------------------------------------------------------
__global__ void __launch_bounds__(256) pw_kernel(const float* __restrict__ x,
                                                 const float* __restrict__ pw,
                                                 const float* __restrict__ pb,
                                                 float* __restrict__ out) {
    __shared__ float sh_y[72][52];   // chunk of 72 input channels x 49 pix
    __shared__ float sh_w[48][72];   // 48 out channels x chunk

    const int win = blockIdx.x;
    const int tid = threadIdx.x;

    float acc[10];
    {
        int c = 0;
        for (int oi = tid; oi < CC * DD; oi += 256) acc[c++] = 0.f;
    }

    for (int i0 = 0; i0 < C3; i0 += 72) {
        __syncthreads();
        for (int idx = tid; idx < 72 * DD; idx += 256) {
            int i = idx / DD, p = idx - i * DD;
            sh_y[i][p] = g_yhat[(win * C3 + i0 + i) * DP + p];
        }
        for (int idx = tid; idx < CC * 72; idx += 256) {
            int o = idx / 72, ii = idx - o * 72;
            sh_w[o][ii] = pw[o * C3 + i0 + ii];
        }
        __syncthreads();
        int c = 0;
        for (int oi = tid; oi < CC * DD; oi += 256, c++) {
            int o = oi / DD, p = oi - o * DD;
            float a = acc[c];
            #pragma unroll 8
            for (int ii = 0; ii < 72; ii++) a += sh_w[o][ii] * sh_y[ii][p];
            acc[c] = a;
        }
    }

    const int wh = win >> 3, wwi = win & 7;
    int c = 0;
    for (int oi = tid; oi < CC * DD; oi += 256, c++) {
        int o = oi / DD, p = oi - o * DD;
        int h = wh * 7 + p / 7;
        int w = wwi * 7 + (p % 7);
        int gi = o * HW + h * WW + w;
        out[gi] = x[gi] + pb[o] + acc[c];
    }
}

// ---------------------------------------------------------------------------
extern "C" void kernel_launch(void* const* d_in, const int* in_sizes, int n_in,
                              void* d_out, int out_size) {
    const float* x  = (const float*)d_in[0];
    const float* w3 = (const float*)d_in[1];
    const float* w5 = (const float*)d_in[2];
    const float* w7 = (const float*)d_in[3];
    const float* pw = (const float*)d_in[4];
    const float* pb = (const float*)d_in[5];
    float* out = (float*)d_out;

    cudaFuncSetAttribute(attn_kernel,
                         cudaFuncAttributeMaxDynamicSharedMemorySize,
                         ATTN_SMEM_BYTES);

    conv_kernel<<<(C3 * HW + 255) / 256, 256>>>(x, w3, w5, w7);
    attn_kernel<<<NR / BM, 256, ATTN_SMEM_BYTES>>>();
    pw_kernel<<<64, 256>>>(x, pw, pb, out);
}

// round 3
// speedup vs baseline: 8.1600x; 8.1600x over previous
#include <cuda_runtime.h>
#include <cuda_bf16.h>
#include <stdint.h>

#define CC 48
#define C3 144
#define HH 56
#define WW 56
#define HW 3136
#define NR 9216
#define DD 49
#define NT 36                     // key tiles per half
#define CEXP 0.029442755936583f   // log2(e)/49

// ---------------- device scratch (allocation-free) ----------------
__device__ __nv_bfloat16 g_qk[NR * 64];      // yf bf16 [row][64], cols 49..63 zero
__device__ float g_opart[4 * NR * 64];       // raw partial O (4 partials)
__device__ float g_den[4 * NR];              // partial denominators
__device__ float g_yhat[NR * 64];            // normalized attention output

// ---------------- PTX helpers ----------------
__device__ __forceinline__ uint32_t smem_u32(const void* p) {
    uint32_t a;
    asm("{ .reg .u64 t; cvta.to.shared.u64 t, %1; cvt.u32.u64 %0, t; }"
        : "=r"(a) : "l"(p));
    return a;
}
#define SW128(o) ((o) ^ (((o) >> 3) & 0x70))

#define CP_ASYNC16(dst, src) \
    asm volatile("cp.async.cg.shared.global [%0], [%1], 16;" :: "r"(dst), "l"(src))
#define CP_COMMIT() asm volatile("cp.async.commit_group;" ::: "memory")
#define CP_WAIT0()  asm volatile("cp.async.wait_group 0;" ::: "memory")
#define CP_WAIT1()  asm volatile("cp.async.wait_group 1;" ::: "memory")

#define LDSM_X4(r0, r1, r2, r3, a) \
    asm volatile("ldmatrix.sync.aligned.m8n8.x4.shared.b16 {%0,%1,%2,%3}, [%4];" \
                 : "=r"(r0), "=r"(r1), "=r"(r2), "=r"(r3) : "r"(a))
#define LDSM_X4T(r0, r1, r2, r3, a) \
    asm volatile("ldmatrix.sync.aligned.m8n8.x4.trans.shared.b16 {%0,%1,%2,%3}, [%4];" \
                 : "=r"(r0), "=r"(r1), "=r"(r2), "=r"(r3) : "r"(a))

#define MMA(d, a0, a1, a2, a3, b0, b1) \
    asm volatile("mma.sync.aligned.m16n8k16.row.col.f32.bf16.bf16.f32 " \
                 "{%0,%1,%2,%3}, {%4,%5,%6,%7}, {%8,%9}, {%0,%1,%2,%3};" \
                 : "+f"((d)[0]), "+f"((d)[1]), "+f"((d)[2]), "+f"((d)[3]) \
                 : "r"(a0), "r"(a1), "r"(a2), "r"(a3), "r"(b0), "r"(b1))

__device__ __forceinline__ uint32_t pack_bf16(float lo, float hi) {
    uint32_t d;
    asm("cvt.rn.bf16x2.f32 %0, %1, %2;" : "=r"(d) : "f"(hi), "f"(lo));
    return d;
}

// ---------------------------------------------------------------------------
// Kernel A: depthwise convs -> bf16 yf rows (flat reshape indexing).
// ---------------------------------------------------------------------------
__global__ void conv_kernel(const float* __restrict__ x,
                            const float* __restrict__ w3,
                            const float* __restrict__ w5,
                            const float* __restrict__ w7) {
    int idx = blockIdx.x * blockDim.x + threadIdx.x;
    if (idx < NR * 15) {                       // zero the pad cols 49..63
        int r = idx / 15, c = idx - r * 15;
        g_qk[r * 64 + 49 + c] = __float2bfloat16(0.f);
    }
    if (idx >= C3 * HW) return;
    int c3  = idx / HW;
    int rem = idx - c3 * HW;
    int h = rem / WW;
    int w = rem - h * WW;
    int b = c3 / CC;
    int c = c3 - b * CC;
    int R = b + 1;
    int ks = 2 * R + 1;
    const float* wp = (b == 0 ? w3 : (b == 1 ? w5 : w7)) + c * ks * ks;
    const float* xc = x + c * HW;
    float sum = 0.f;
    #pragma unroll 1
    for (int dh = -R; dh <= R; dh++) {
        int hh = h + dh;
        if (hh < 0 || hh >= HH) continue;
        const float* xr = xc + hh * WW;
        const float* wr = wp + (dh + R) * ks + R;
        #pragma unroll 1
        for (int dw = -R; dw <= R; dw++) {
            int ww = w + dw;
            if (ww < 0 || ww >= WW) continue;
            sum += xr[ww] * wr[dw];
        }
    }
    int lin = h * WW + w;
    int g = lin / DD;
    int p = lin - g * DD;
    g_qk[(g * C3 + c3) * 64 + p] = __float2bfloat16(sum);
}

// ---------------------------------------------------------------------------
// Kernel B: HMMA flash attention. 8 warps = 4(m) x 2(n).
// SMEM: Q tile 16K + K double buffer 2x16K = 48K.
// ---------------------------------------------------------------------------
__global__ void __launch_bounds__(256, 1) attn_kernel() {
    extern __shared__ char smraw[];
    const uint32_t SB  = smem_u32(smraw);
    const uint32_t QB  = SB;
    const uint32_t KB0 = SB + 16384;

    const int tid  = threadIdx.x;
    const int lane = tid & 31;
    const int wid  = tid >> 5;
    const int wm = wid >> 1, wn = wid & 1;
    const int g = lane >> 2, tig = lane & 3;
    const int bq = blockIdx.x >> 1, half = blockIdx.x & 1;
    const int q0 = bq * 128;

    // per-lane ldmatrix address constants
    const int l7 = lane & 7;
    const uint32_t xm   = (uint32_t)(l7 << 4);                         // swizzle xor
    const uint32_t aoff = (uint32_t)((wm * 32 + l7 + ((lane & 8) ? 8 : 0)) * 128);
    const uint32_t ahi  = (lane & 16) ? 16u : 0u;
    const uint32_t bsb  = (uint32_t)((wn * 64 + l7 + ((lane & 16) ? 8 : 0)) * 128);
    const uint32_t bshi = (lane & 8) ? 16u : 0u;
    const uint32_t bvb  = (uint32_t)((wn * 64 + l7 + ((lane & 8) ? 8 : 0)) * 128);
    const uint32_t bvhi = (lane & 16) ? 16u : 0u;

    // ---- async loads: Q tile, then K tile 0 ----
    {
        const char* src = (const char*)g_qk + (size_t)q0 * 128;
        #pragma unroll
        for (int it = 0; it < 4; it++) {
            int idx = it * 256 + tid;
            int r = idx >> 3, c = idx & 7;
            CP_ASYNC16(QB + SW128((uint32_t)(r * 128 + c * 16)), src + r * 128 + c * 16);
        }
        CP_COMMIT();
    }
    {
        const char* src = (const char*)g_qk + (size_t)(half * 4608) * 128;
        #pragma unroll
        for (int it = 0; it < 4; it++) {
            int idx = it * 256 + tid;
            int r = idx >> 3, c = idx & 7;
            CP_ASYNC16(KB0 + SW128((uint32_t)(r * 128 + c * 16)), src + r * 128 + c * 16);
        }
        CP_COMMIT();
    }

    float Ov[2][8][4] = {};
    float dden[2][2] = {};

    for (int t = 0; t < NT; t++) {
        if (t + 1 < NT) {
            const uint32_t kb = KB0 + (uint32_t)(((t + 1) & 1) * 16384);
            const char* src = (const char*)g_qk + (size_t)(half * 4608 + (t + 1) * 128) * 128;
            #pragma unroll
            for (int it = 0; it < 4; it++) {
                int idx = it * 256 + tid;
                int r = idx >> 3, c = idx & 7;
                CP_ASYNC16(kb + SW128((uint32_t)(r * 128 + c * 16)), src + r * 128 + c * 16);
            }
            CP_COMMIT();
            CP_WAIT1();
        } else {
            CP_WAIT0();
        }
        __syncthreads();

        const uint32_t KB = KB0 + (uint32_t)((t & 1) * 16384);

        // ---- S = Q K^T ----
        float Cs[2][8][4] = {};
        #pragma unroll
        for (int ks = 0; ks < 4; ks++) {
            uint32_t A0[4], A1[4];
            uint32_t ac = (uint32_t)(ks * 32 + ahi) ^ xm;
            LDSM_X4(A0[0], A0[1], A0[2], A0[3], QB + aoff + ac);
            LDSM_X4(A1[0], A1[1], A1[2], A1[3], QB + aoff + 2048 + ac);
            uint32_t bc = (uint32_t)(ks * 32 + bshi) ^ xm;
            #pragma unroll
            for (int np = 0; np < 4; np++) {
                uint32_t B[4];
                LDSM_X4(B[0], B[1], B[2], B[3], KB + bsb + (uint32_t)(np * 2048) + bc);
                MMA(Cs[0][2 * np],     A0[0], A0[1], A0[2], A0[3], B[0], B[1]);
                MMA(Cs[0][2 * np + 1], A0[0], A0[1], A0[2], A0[3], B[2], B[3]);
                MMA(Cs[1][2 * np],     A1[0], A1[1], A1[2], A1[3], B[0], B[1]);
                MMA(Cs[1][2 * np + 1], A1[0], A1[1], A1[2], A1[3], B[2], B[3]);
            }
        }

        // ---- P = exp(S/49) in registers; pack to bf16 A fragments ----
        uint32_t aP[2][4][4];
        #pragma unroll
        for (int m = 0; m < 2; m++) {
            #pragma unroll
            for (int nt = 0; nt < 8; nt++) {
                float e0 = exp2f(Cs[m][nt][0] * CEXP);
                float e1 = exp2f(Cs[m][nt][1] * CEXP);
                float e2 = exp2f(Cs[m][nt][2] * CEXP);
                float e3 = exp2f(Cs[m][nt][3] * CEXP);
                dden[m][0] += e0 + e1;
                dden[m][1] += e2 + e3;
                int kk = nt >> 1;
                if ((nt & 1) == 0) {
                    aP[m][kk][0] = pack_bf16(e0, e1);
                    aP[m][kk][1] = pack_bf16(e2, e3);
                } else {
                    aP[m][kk][2] = pack_bf16(e0, e1);
                    aP[m][kk][3] = pack_bf16(e2, e3);
                }
            }
        }

        // ---- O += P V  (V rows = K rows; .trans ldmatrix for B) ----
        #pragma unroll
        for (int ks = 0; ks < 4; ks++) {
            #pragma unroll
            for (int dp = 0; dp < 4; dp++) {
                uint32_t B[4];
                LDSM_X4T(B[0], B[1], B[2], B[3],
                         KB + bvb + (uint32_t)(ks * 2048) +
                         (((uint32_t)(dp * 32 + bvhi)) ^ xm));
                MMA(Ov[0][2 * dp],     aP[0][ks][0], aP[0][ks][1], aP[0][ks][2], aP[0][ks][3], B[0], B[1]);
                MMA(Ov[0][2 * dp + 1], aP[0][ks][0], aP[0][ks][1], aP[0][ks][2], aP[0][ks][3], B[2], B[3]);
                MMA(Ov[1][2 * dp],     aP[1][ks][0], aP[1][ks][1], aP[1][ks][2], aP[1][ks][3], B[0], B[1]);
                MMA(Ov[1][2 * dp + 1], aP[1][ks][0], aP[1][ks][1], aP[1][ks][2], aP[1][ks][3], B[2], B[3]);
            }
        }
        __syncthreads();
    }

    // ---- denominator reduce over tig lanes, write partials ----
    const int part = half * 2 + wn;
    #pragma unroll
    for (int m = 0; m < 2; m++) {
        #pragma unroll
        for (int i = 0; i < 2; i++) {
            float v = dden[m][i];
            v += __shfl_xor_sync(0xFFFFFFFFu, v, 1);
            v += __shfl_xor_sync(0xFFFFFFFFu, v, 2);
            if (tig == 0)
                g_den[part * NR + q0 + wm * 32 + m * 16 + g + i * 8] = v;
        }
    }

    // ---- store raw partial O (cols 0..55; 56..63 stay zero) ----
    #pragma unroll
    for (int m = 0; m < 2; m++) {
        int r0 = q0 + wm * 32 + m * 16 + g;
        float* base = g_opart + ((size_t)part * NR + r0) * 64;
        #pragma unroll
        for (int nt = 0; nt < 7; nt++) {
            int col = nt * 8 + 2 * tig;
            *(float2*)(base + col)            = make_float2(Ov[m][nt][0], Ov[m][nt][1]);
            *(float2*)(base + 8 * 64 + col)   = make_float2(Ov[m][nt][2], Ov[m][nt][3]);
        }
    }
}

// ---------------------------------------------------------------------------
// Kernel C: combine 4 partials + normalize.
// ---------------------------------------------------------------------------
__global__ void combine_kernel() {
    int i = blockIdx.x * 256 + threadIdx.x;
    if (i >= NR * 64) return;
    int r = i >> 6;
    float num = g_opart[i] + g_opart[NR * 64 + i] +
                g_opart[2 * NR * 64 + i] + g_opart[3 * NR * 64 + i];
    float den = g_den[r] + g_den[NR + r] + g_den[2 * NR + r] + g_den[3 * NR + r];
    g_yhat[i] = num / den;
}

// ---------------------------------------------------------------------------
// Kernel D: pointwise conv + bias + residual (spatial 7x7 inverse map).
// ---------------------------------------------------------------------------
__global__ void __launch_bounds__(256) pw_kernel(const float* __restrict__ x,
                                                 const float* __restrict__ pw,
                                                 const float* __restrict__ pb,
                                                 float* __restrict__ out) {
    __shared__ float sh_y[72][52];
    __shared__ float sh_w[48][72];

    const int win = blockIdx.x;
    const int tid = threadIdx.x;

    float acc[10];
    {
        int c = 0;
        for (int oi = tid; oi < CC * DD; oi += 256) acc[c++] = 0.f;
    }

    for (int i0 = 0; i0 < C3; i0 += 72) {
        __syncthreads();
        for (int idx = tid; idx < 72 * DD; idx += 256) {
            int i = idx / DD, p = idx - i * DD;
            sh_y[i][p] = g_yhat[(win * C3 + i0 + i) * 64 + p];
        }
        for (int idx = tid; idx < CC * 72; idx += 256) {
            int o = idx / 72, ii = idx - o * 72;
            sh_w[o][ii] = pw[o * C3 + i0 + ii];
        }
        __syncthreads();
        int c = 0;
        for (int oi = tid; oi < CC * DD; oi += 256, c++) {
            int o = oi / DD, p = oi - o * DD;
            float a = acc[c];
            #pragma unroll 8
            for (int ii = 0; ii < 72; ii++) a += sh_w[o][ii] * sh_y[ii][p];
            acc[c] = a;
        }
    }

    const int wh = win >> 3, wwi = win & 7;
    int c = 0;
    for (int oi = tid; oi < CC * DD; oi += 256, c++) {
        int o = oi / DD, p = oi - o * DD;
        int h = wh * 7 + p / 7;
        int w = wwi * 7 + (p % 7);
        int gi = o * HW + h * WW + w;
        out[gi] = x[gi] + pb[o] + acc[c];
    }
}

// ---------------------------------------------------------------------------
extern "C" void kernel_launch(void* const* d_in, const int* in_sizes, int n_in,
                              void* d_out, int out_size) {
    const float* x  = (const float*)d_in[0];
    const float* w3 = (const float*)d_in[1];
    const float* w5 = (const float*)d_in[2];
    const float* w7 = (const float*)d_in[3];
    const float* pw = (const float*)d_in[4];
    const float* pb = (const float*)d_in[5];
    float* out = (float*)d_out;

    cudaFuncSetAttribute(attn_kernel,
                         cudaFuncAttributeMaxDynamicSharedMemorySize, 49152);

    conv_kernel<<<(C3 * HW + 255) / 256, 256>>>(x, w3, w5, w7);
    attn_kernel<<<144, 256, 49152>>>();
    combine_kernel<<<(NR * 64 + 255) / 256, 256>>>();
    pw_kernel<<<64, 256>>>(x, pw, pb, out);
}

// round 4
// speedup vs baseline: 10.6479x; 1.3049x over previous
#include <cuda_runtime.h>
#include <cuda_bf16.h>
#include <stdint.h>

#define CC 48
#define C3 144
#define HH 56
#define WW 56
#define HW 3136
#define NR 9216
#define DD 49
#define NT 36                     // key tiles per half
#define CEXP 0.029442755936583f   // log2(e)/49

// ---------------- device scratch (allocation-free) ----------------
__device__ __nv_bfloat16 g_qk[NR * 64];      // yf bf16 [row][64], cols 49..63 zero
__device__ float g_opart[4 * NR * 64];       // raw partial O (4 partials)
__device__ float g_den[4 * NR];              // partial denominators
__device__ float g_yhat[NR * 64];            // normalized attention output (cols 0..55)

// ---------------- PTX helpers ----------------
__device__ __forceinline__ uint32_t smem_u32(const void* p) {
    uint32_t a;
    asm("{ .reg .u64 t; cvta.to.shared.u64 t, %1; cvt.u32.u64 %0, t; }"
        : "=r"(a) : "l"(p));
    return a;
}
#define SW128(o) ((o) ^ (((o) >> 3) & 0x70))

#define CP_ASYNC16(dst, src) \
    asm volatile("cp.async.cg.shared.global [%0], [%1], 16;" :: "r"(dst), "l"(src))
#define CP_COMMIT() asm volatile("cp.async.commit_group;" ::: "memory")
#define CP_WAIT0()  asm volatile("cp.async.wait_group 0;" ::: "memory")
#define CP_WAIT1()  asm volatile("cp.async.wait_group 1;" ::: "memory")

#define LDSM_X4(r0, r1, r2, r3, a) \
    asm volatile("ldmatrix.sync.aligned.m8n8.x4.shared.b16 {%0,%1,%2,%3}, [%4];" \
                 : "=r"(r0), "=r"(r1), "=r"(r2), "=r"(r3) : "r"(a))
#define LDSM_X4T(r0, r1, r2, r3, a) \
    asm volatile("ldmatrix.sync.aligned.m8n8.x4.trans.shared.b16 {%0,%1,%2,%3}, [%4];" \
                 : "=r"(r0), "=r"(r1), "=r"(r2), "=r"(r3) : "r"(a))

#define MMA(d, a0, a1, a2, a3, b0, b1) \
    asm volatile("mma.sync.aligned.m16n8k16.row.col.f32.bf16.bf16.f32 " \
                 "{%0,%1,%2,%3}, {%4,%5,%6,%7}, {%8,%9}, {%0,%1,%2,%3};" \
                 : "+f"((d)[0]), "+f"((d)[1]), "+f"((d)[2]), "+f"((d)[3]) \
                 : "r"(a0), "r"(a1), "r"(a2), "r"(a3), "r"(b0), "r"(b1))

__device__ __forceinline__ uint32_t pack_bf16(float lo, float hi) {
    uint32_t d;
    asm("cvt.rn.bf16x2.f32 %0, %1, %2;" : "=r"(d) : "f"(hi), "f"(lo));
    return d;
}

// ---------------------------------------------------------------------------
// Kernel A: depthwise convs, smem-tiled. Grid = 48 channels x 8 row-strips.
// Zero-padded halo tile -> no bounds checks; fully unrolled per kernel size.
// ---------------------------------------------------------------------------
__global__ void __launch_bounds__(256) conv_kernel(const float* __restrict__ x,
                                                   const float* __restrict__ w3,
                                                   const float* __restrict__ w5,
                                                   const float* __restrict__ w7) {
    __shared__ float xs[13][64];   // rows h0-3 .. h0+9, cols -3..60 (offset +3)
    __shared__ float sw[83];       // w3[9] | w5[25] | w7[49]

    const int tid = threadIdx.x;
    const int c   = blockIdx.x >> 3;
    const int h0  = (blockIdx.x & 7) * 7;

    // zero-fill pad cols 49..63 of g_qk (grid-stride, once per launch)
    for (int j = blockIdx.x * 256 + tid; j < NR * 15; j += 384 * 256) {
        int r = j / 15, cc = j - r * 15;
        g_qk[r * 64 + 49 + cc] = __float2bfloat16(0.f);
    }

    // load padded x tile
    const float* xc = x + c * HW;
    for (int idx = tid; idx < 13 * 64; idx += 256) {
        int r = idx >> 6, wc = idx & 63;
        int hh = h0 - 3 + r, w = wc - 3;
        float v = 0.f;
        if (hh >= 0 && hh < HH && w >= 0 && w < WW) v = xc[hh * WW + w];
        xs[r][wc] = v;
    }
    // load weights
    if (tid < 83) {
        float v;
        if (tid < 9)       v = w3[c * 9 + tid];
        else if (tid < 34) v = w5[c * 25 + tid - 9];
        else               v = w7[c * 49 + tid - 34];
        sw[tid] = v;
    }
    __syncthreads();

    for (int idx = tid; idx < 3 * 7 * WW; idx += 256) {
        int b   = idx / 392;
        int rem = idx - b * 392;
        int ho  = rem / WW;
        int w   = rem - ho * WW;
        float sum = 0.f;
        if (b == 0) {
            const float* wp = sw;
            #pragma unroll
            for (int dh = 0; dh < 3; dh++)
                #pragma unroll
                for (int dw = 0; dw < 3; dw++)
                    sum += xs[ho + 2 + dh][w + 2 + dw] * wp[dh * 3 + dw];
        } else if (b == 1) {
            const float* wp = sw + 9;
            #pragma unroll
            for (int dh = 0; dh < 5; dh++)
                #pragma unroll
                for (int dw = 0; dw < 5; dw++)
                    sum += xs[ho + 1 + dh][w + 1 + dw] * wp[dh * 5 + dw];
        } else {
            const float* wp = sw + 34;
            #pragma unroll
            for (int dh = 0; dh < 7; dh++)
                #pragma unroll
                for (int dw = 0; dw < 7; dw++)
                    sum += xs[ho + dh][w + dw] * wp[dh * 7 + dw];
        }
        int h   = h0 + ho;
        int lin = h * WW + w;
        int g   = lin / DD;
        int p   = lin - g * DD;
        int c3  = b * CC + c;
        g_qk[(g * C3 + c3) * 64 + p] = __float2bfloat16(sum);
    }
}

// ---------------------------------------------------------------------------
// Kernel B: HMMA flash attention. 8 warps = 4(m) x 2(n).
// ---------------------------------------------------------------------------
__global__ void __launch_bounds__(256, 1) attn_kernel() {
    extern __shared__ char smraw[];
    const uint32_t SB  = smem_u32(smraw);
    const uint32_t QB  = SB;
    const uint32_t KB0 = SB + 16384;

    const int tid  = threadIdx.x;
    const int lane = tid & 31;
    const int wid  = tid >> 5;
    const int wm = wid >> 1, wn = wid & 1;
    const int g = lane >> 2, tig = lane & 3;
    const int bq = blockIdx.x >> 1, half = blockIdx.x & 1;
    const int q0 = bq * 128;

    const int l7 = lane & 7;
    const uint32_t xm   = (uint32_t)(l7 << 4);
    const uint32_t aoff = (uint32_t)((wm * 32 + l7 + ((lane & 8) ? 8 : 0)) * 128);
    const uint32_t ahi  = (lane & 16) ? 16u : 0u;
    const uint32_t bsb  = (uint32_t)((wn * 64 + l7 + ((lane & 16) ? 8 : 0)) * 128);
    const uint32_t bshi = (lane & 8) ? 16u : 0u;
    const uint32_t bvb  = (uint32_t)((wn * 64 + l7 + ((lane & 8) ? 8 : 0)) * 128);
    const uint32_t bvhi = (lane & 16) ? 16u : 0u;

    {
        const char* src = (const char*)g_qk + (size_t)q0 * 128;
        #pragma unroll
        for (int it = 0; it < 4; it++) {
            int idx = it * 256 + tid;
            int r = idx >> 3, c = idx & 7;
            CP_ASYNC16(QB + SW128((uint32_t)(r * 128 + c * 16)), src + r * 128 + c * 16);
        }
        CP_COMMIT();
    }
    {
        const char* src = (const char*)g_qk + (size_t)(half * 4608) * 128;
        #pragma unroll
        for (int it = 0; it < 4; it++) {
            int idx = it * 256 + tid;
            int r = idx >> 3, c = idx & 7;
            CP_ASYNC16(KB0 + SW128((uint32_t)(r * 128 + c * 16)), src + r * 128 + c * 16);
        }
        CP_COMMIT();
    }

    float Ov[2][7][4] = {};
    float dden[2][2] = {};

    for (int t = 0; t < NT; t++) {
        if (t + 1 < NT) {
            const uint32_t kb = KB0 + (uint32_t)(((t + 1) & 1) * 16384);
            const char* src = (const char*)g_qk + (size_t)(half * 4608 + (t + 1) * 128) * 128;
            #pragma unroll
            for (int it = 0; it < 4; it++) {
                int idx = it * 256 + tid;
                int r = idx >> 3, c = idx & 7;
                CP_ASYNC16(kb + SW128((uint32_t)(r * 128 + c * 16)), src + r * 128 + c * 16);
            }
            CP_COMMIT();
            CP_WAIT1();
        } else {
            CP_WAIT0();
        }
        __syncthreads();

        const uint32_t KB = KB0 + (uint32_t)((t & 1) * 16384);

        // ---- S = Q K^T ----
        float Cs[2][8][4] = {};
        #pragma unroll
        for (int ks = 0; ks < 4; ks++) {
            uint32_t A0[4], A1[4];
            uint32_t ac = (uint32_t)(ks * 32 + ahi) ^ xm;
            LDSM_X4(A0[0], A0[1], A0[2], A0[3], QB + aoff + ac);
            LDSM_X4(A1[0], A1[1], A1[2], A1[3], QB + aoff + 2048 + ac);
            uint32_t bc = (uint32_t)(ks * 32 + bshi) ^ xm;
            #pragma unroll
            for (int np = 0; np < 4; np++) {
                uint32_t B[4];
                LDSM_X4(B[0], B[1], B[2], B[3], KB + bsb + (uint32_t)(np * 2048) + bc);
                MMA(Cs[0][2 * np],     A0[0], A0[1], A0[2], A0[3], B[0], B[1]);
                MMA(Cs[0][2 * np + 1], A0[0], A0[1], A0[2], A0[3], B[2], B[3]);
                MMA(Cs[1][2 * np],     A1[0], A1[1], A1[2], A1[3], B[0], B[1]);
                MMA(Cs[1][2 * np + 1], A1[0], A1[1], A1[2], A1[3], B[2], B[3]);
            }
        }

        // ---- P = exp(S/49) in registers; pack to bf16 A fragments ----
        uint32_t aP[2][4][4];
        #pragma unroll
        for (int m = 0; m < 2; m++) {
            #pragma unroll
            for (int nt = 0; nt < 8; nt++) {
                float e0 = exp2f(Cs[m][nt][0] * CEXP);
                float e1 = exp2f(Cs[m][nt][1] * CEXP);
                float e2 = exp2f(Cs[m][nt][2] * CEXP);
                float e3 = exp2f(Cs[m][nt][3] * CEXP);
                dden[m][0] += e0 + e1;
                dden[m][1] += e2 + e3;
                int kk = nt >> 1;
                if ((nt & 1) == 0) {
                    aP[m][kk][0] = pack_bf16(e0, e1);
                    aP[m][kk][1] = pack_bf16(e2, e3);
                } else {
                    aP[m][kk][2] = pack_bf16(e0, e1);
                    aP[m][kk][3] = pack_bf16(e2, e3);
                }
            }
        }

        // ---- O += P V (cols 56..63 never stored -> skip their MMAs) ----
        #pragma unroll
        for (int ks = 0; ks < 4; ks++) {
            #pragma unroll
            for (int dp = 0; dp < 4; dp++) {
                uint32_t B[4];
                LDSM_X4T(B[0], B[1], B[2], B[3],
                         KB + bvb + (uint32_t)(ks * 2048) +
                         (((uint32_t)(dp * 32 + bvhi)) ^ xm));
                MMA(Ov[0][2 * dp], aP[0][ks][0], aP[0][ks][1], aP[0][ks][2], aP[0][ks][3], B[0], B[1]);
                MMA(Ov[1][2 * dp], aP[1][ks][0], aP[1][ks][1], aP[1][ks][2], aP[1][ks][3], B[0], B[1]);
                if (dp < 3) {
                    MMA(Ov[0][2 * dp + 1], aP[0][ks][0], aP[0][ks][1], aP[0][ks][2], aP[0][ks][3], B[2], B[3]);
                    MMA(Ov[1][2 * dp + 1], aP[1][ks][0], aP[1][ks][1], aP[1][ks][2], aP[1][ks][3], B[2], B[3]);
                }
            }
        }
        __syncthreads();
    }

    const int part = half * 2 + wn;
    #pragma unroll
    for (int m = 0; m < 2; m++) {
        #pragma unroll
        for (int i = 0; i < 2; i++) {
            float v = dden[m][i];
            v += __shfl_xor_sync(0xFFFFFFFFu, v, 1);
            v += __shfl_xor_sync(0xFFFFFFFFu, v, 2);
            if (tig == 0)
                g_den[part * NR + q0 + wm * 32 + m * 16 + g + i * 8] = v;
        }
    }

    #pragma unroll
    for (int m = 0; m < 2; m++) {
        int r0 = q0 + wm * 32 + m * 16 + g;
        float* base = g_opart + ((size_t)part * NR + r0) * 64;
        #pragma unroll
        for (int nt = 0; nt < 7; nt++) {
            int col = nt * 8 + 2 * tig;
            *(float2*)(base + col)          = make_float2(Ov[m][nt][0], Ov[m][nt][1]);
            *(float2*)(base + 8 * 64 + col) = make_float2(Ov[m][nt][2], Ov[m][nt][3]);
        }
    }
}

// ---------------------------------------------------------------------------
// Kernel C: combine 4 partials + normalize (cols 0..55 only, float4).
// ---------------------------------------------------------------------------
__global__ void combine_kernel() {
    int idx = blockIdx.x * 256 + threadIdx.x;
    if (idx >= NR * 14) return;
    int r = idx / 14, q = idx - r * 14;
    int base = r * 64 + 4 * q;
    const float4* p0 = (const float4*)(g_opart + base);
    const float4* p1 = (const float4*)(g_opart + NR * 64 + base);
    const float4* p2 = (const float4*)(g_opart + 2 * NR * 64 + base);
    const float4* p3 = (const float4*)(g_opart + 3 * NR * 64 + base);
    float4 a = *p0, b = *p1, c = *p2, d = *p3;
    float rd = 1.0f / (g_den[r] + g_den[NR + r] + g_den[2 * NR + r] + g_den[3 * NR + r]);
    float4 o;
    o.x = (a.x + b.x + c.x + d.x) * rd;
    o.y = (a.y + b.y + c.y + d.y) * rd;
    o.z = (a.z + b.z + c.z + d.z) * rd;
    o.w = (a.w + b.w + c.w + d.w) * rd;
    *(float4*)(g_yhat + base) = o;
}

// ---------------------------------------------------------------------------
// Kernel D: pointwise conv + bias + residual. Grid = 64 windows x 3 o-groups.
// Full 144-channel chunk in smem; 1x4 register tiling.
// ---------------------------------------------------------------------------
__global__ void __launch_bounds__(256) pw_kernel(const float* __restrict__ x,
                                                 const float* __restrict__ pw,
                                                 const float* __restrict__ pb,
                                                 float* __restrict__ out) {
    __shared__ float sh_y[C3][52];
    __shared__ float sh_w[16][C3];

    const int win = blockIdx.x / 3;
    const int og  = blockIdx.x - win * 3;
    const int tid = threadIdx.x;

    // load yhat chunk [144][52] as float4
    for (int idx = tid; idx < C3 * 13; idx += 256) {
        int i = idx / 13, q = idx - i * 13;
        *(float4*)&sh_y[i][4 * q] = *(const float4*)(g_yhat + (win * C3 + i) * 64 + 4 * q);
    }
    // load weights for 16 out channels
    for (int idx = tid; idx < 16 * C3; idx += 256) {
        int o = idx / C3, ii = idx - o * C3;
        sh_w[o][ii] = pw[(og * 16 + o) * C3 + ii];
    }
    __syncthreads();

    if (tid < 208) {                    // 16 o x 13 p-groups
        const int o  = tid / 13;
        const int pg = tid - o * 13;
        const int p0 = 4 * pg;
        float4 acc = make_float4(0.f, 0.f, 0.f, 0.f);
        #pragma unroll 8
        for (int ii = 0; ii < C3; ii++) {
            float w = sh_w[o][ii];
            float4 y = *(const float4*)&sh_y[ii][p0];
            acc.x += w * y.x; acc.y += w * y.y; acc.z += w * y.z; acc.w += w * y.w;
        }
        const int oo = og * 16 + o;
        const float bias = pb[oo];
        const int wh = win >> 3, wwi = win & 7;
        float av[4] = {acc.x, acc.y, acc.z, acc.w};
        #pragma unroll
        for (int j = 0; j < 4; j++) {
            int p = p0 + j;
            if (p < DD) {
                int h = wh * 7 + p / 7;
                int w = wwi * 7 + (p % 7);
                int gi = oo * HW + h * WW + w;
                out[gi] = x[gi] + bias + av[j];
            }
        }
    }
}

// ---------------------------------------------------------------------------
extern "C" void kernel_launch(void* const* d_in, const int* in_sizes, int n_in,
                              void* d_out, int out_size) {
    const float* x  = (const float*)d_in[0];
    const float* w3 = (const float*)d_in[1];
    const float* w5 = (const float*)d_in[2];
    const float* w7 = (const float*)d_in[3];
    const float* pw = (const float*)d_in[4];
    const float* pb = (const float*)d_in[5];
    float* out = (float*)d_out;

    cudaFuncSetAttribute(attn_kernel,
                         cudaFuncAttributeMaxDynamicSharedMemorySize, 49152);

    conv_kernel<<<384, 256>>>(x, w3, w5, w7);
    attn_kernel<<<144, 256, 49152>>>();
    combine_kernel<<<(NR * 14 + 255) / 256, 256>>>();
    pw_kernel<<<192, 256>>>(x, pw, pb, out);
}

// round 5
// speedup vs baseline: 11.8945x; 1.1171x over previous
#include <cuda_runtime.h>
#include <cuda_bf16.h>
#include <stdint.h>

#define CC 48
#define C3 144
#define HH 56
#define WW 56
#define HW 3136
#define NR 9216
#define DD 49
#define NT 36                     // key tiles per half
#define CEXP 0.029442755936583f   // log2(e)/49

// ---------------- device scratch (allocation-free) ----------------
__device__ __nv_bfloat16 g_qk[NR * 64];      // yf bf16 [row][64], cols 49..63 zero
__device__ float g_opart[4 * NR * 64];       // raw partial O (4 partials)
__device__ float g_den[4 * NR];              // partial denominators
__device__ float g_pwpart[2 * 64 * CC * 52]; // pw partial sums [ig][win][o][52]

// ---------------- PTX helpers ----------------
__device__ __forceinline__ uint32_t smem_u32(const void* p) {
    uint32_t a;
    asm("{ .reg .u64 t; cvta.to.shared.u64 t, %1; cvt.u32.u64 %0, t; }"
        : "=r"(a) : "l"(p));
    return a;
}
#define SW128(o) ((o) ^ (((o) >> 3) & 0x70))

__device__ __forceinline__ float fast_ex2(float x) {
    float y;
    asm("ex2.approx.ftz.f32 %0, %1;" : "=f"(y) : "f"(x));
    return y;
}
__device__ __forceinline__ float fast_rcp(float x) {
    float y;
    asm("rcp.approx.ftz.f32 %0, %1;" : "=f"(y) : "f"(x));
    return y;
}

#define CP_ASYNC16(dst, src) \
    asm volatile("cp.async.cg.shared.global [%0], [%1], 16;" :: "r"(dst), "l"(src))
#define CP_COMMIT() asm volatile("cp.async.commit_group;" ::: "memory")
#define CP_WAIT0()  asm volatile("cp.async.wait_group 0;" ::: "memory")
#define CP_WAIT1()  asm volatile("cp.async.wait_group 1;" ::: "memory")

#define LDSM_X4(r0, r1, r2, r3, a) \
    asm volatile("ldmatrix.sync.aligned.m8n8.x4.shared.b16 {%0,%1,%2,%3}, [%4];" \
                 : "=r"(r0), "=r"(r1), "=r"(r2), "=r"(r3) : "r"(a))
#define LDSM_X4T(r0, r1, r2, r3, a) \
    asm volatile("ldmatrix.sync.aligned.m8n8.x4.trans.shared.b16 {%0,%1,%2,%3}, [%4];" \
                 : "=r"(r0), "=r"(r1), "=r"(r2), "=r"(r3) : "r"(a))

#define MMA(d, a0, a1, a2, a3, b0, b1) \
    asm volatile("mma.sync.aligned.m16n8k16.row.col.f32.bf16.bf16.f32 " \
                 "{%0,%1,%2,%3}, {%4,%5,%6,%7}, {%8,%9}, {%0,%1,%2,%3};" \
                 : "+f"((d)[0]), "+f"((d)[1]), "+f"((d)[2]), "+f"((d)[3]) \
                 : "r"(a0), "r"(a1), "r"(a2), "r"(a3), "r"(b0), "r"(b1))

__device__ __forceinline__ uint32_t pack_bf16(float lo, float hi) {
    uint32_t d;
    asm("cvt.rn.bf16x2.f32 %0, %1, %2;" : "=r"(d) : "f"(hi), "f"(lo));
    return d;
}

// ---------------------------------------------------------------------------
// Kernel A: depthwise convs, smem-tiled. Grid = 48 channels x 8 row-strips.
// ---------------------------------------------------------------------------
__global__ void __launch_bounds__(256) conv_kernel(const float* __restrict__ x,
                                                   const float* __restrict__ w3,
                                                   const float* __restrict__ w5,
                                                   const float* __restrict__ w7) {
    __shared__ float xs[13][64];
    __shared__ float sw[83];

    const int tid = threadIdx.x;
    const int c   = blockIdx.x >> 3;
    const int h0  = (blockIdx.x & 7) * 7;

    for (int j = blockIdx.x * 256 + tid; j < NR * 15; j += 384 * 256) {
        int r = j / 15, cc = j - r * 15;
        g_qk[r * 64 + 49 + cc] = __float2bfloat16(0.f);
    }

    const float* xc = x + c * HW;
    for (int idx = tid; idx < 13 * 64; idx += 256) {
        int r = idx >> 6, wc = idx & 63;
        int hh = h0 - 3 + r, w = wc - 3;
        float v = 0.f;
        if (hh >= 0 && hh < HH && w >= 0 && w < WW) v = xc[hh * WW + w];
        xs[r][wc] = v;
    }
    if (tid < 83) {
        float v;
        if (tid < 9)       v = w3[c * 9 + tid];
        else if (tid < 34) v = w5[c * 25 + tid - 9];
        else               v = w7[c * 49 + tid - 34];
        sw[tid] = v;
    }
    __syncthreads();

    for (int idx = tid; idx < 3 * 7 * WW; idx += 256) {
        int b   = idx / 392;
        int rem = idx - b * 392;
        int ho  = rem / WW;
        int w   = rem - ho * WW;
        float sum = 0.f;
        if (b == 0) {
            const float* wp = sw;
            #pragma unroll
            for (int dh = 0; dh < 3; dh++)
                #pragma unroll
                for (int dw = 0; dw < 3; dw++)
                    sum += xs[ho + 2 + dh][w + 2 + dw] * wp[dh * 3 + dw];
        } else if (b == 1) {
            const float* wp = sw + 9;
            #pragma unroll
            for (int dh = 0; dh < 5; dh++)
                #pragma unroll
                for (int dw = 0; dw < 5; dw++)
                    sum += xs[ho + 1 + dh][w + 1 + dw] * wp[dh * 5 + dw];
        } else {
            const float* wp = sw + 34;
            #pragma unroll
            for (int dh = 0; dh < 7; dh++)
                #pragma unroll
                for (int dw = 0; dw < 7; dw++)
                    sum += xs[ho + dh][w + dw] * wp[dh * 7 + dw];
        }
        int h   = h0 + ho;
        int lin = h * WW + w;
        int g   = lin / DD;
        int p   = lin - g * DD;
        int c3  = b * CC + c;
        g_qk[(g * C3 + c3) * 64 + p] = __float2bfloat16(sum);
    }
}

// ---------------------------------------------------------------------------
// Kernel B: HMMA flash attention. 8 warps = 4(m) x 2(n).
// ---------------------------------------------------------------------------
__global__ void __launch_bounds__(256, 1) attn_kernel() {
    extern __shared__ char smraw[];
    const uint32_t SB  = smem_u32(smraw);
    const uint32_t QB  = SB;
    const uint32_t KB0 = SB + 16384;

    const int tid  = threadIdx.x;
    const int lane = tid & 31;
    const int wid  = tid >> 5;
    const int wm = wid >> 1, wn = wid & 1;
    const int g = lane >> 2, tig = lane & 3;
    const int bq = blockIdx.x >> 1, half = blockIdx.x & 1;
    const int q0 = bq * 128;

    const int l7 = lane & 7;
    const uint32_t xm   = (uint32_t)(l7 << 4);
    const uint32_t aoff = (uint32_t)((wm * 32 + l7 + ((lane & 8) ? 8 : 0)) * 128);
    const uint32_t ahi  = (lane & 16) ? 16u : 0u;
    const uint32_t bsb  = (uint32_t)((wn * 64 + l7 + ((lane & 16) ? 8 : 0)) * 128);
    const uint32_t bshi = (lane & 8) ? 16u : 0u;
    const uint32_t bvb  = (uint32_t)((wn * 64 + l7 + ((lane & 8) ? 8 : 0)) * 128);
    const uint32_t bvhi = (lane & 16) ? 16u : 0u;

    {
        const char* src = (const char*)g_qk + (size_t)q0 * 128;
        #pragma unroll
        for (int it = 0; it < 4; it++) {
            int idx = it * 256 + tid;
            int r = idx >> 3, c = idx & 7;
            CP_ASYNC16(QB + SW128((uint32_t)(r * 128 + c * 16)), src + r * 128 + c * 16);
        }
        CP_COMMIT();
    }
    {
        const char* src = (const char*)g_qk + (size_t)(half * 4608) * 128;
        #pragma unroll
        for (int it = 0; it < 4; it++) {
            int idx = it * 256 + tid;
            int r = idx >> 3, c = idx & 7;
            CP_ASYNC16(KB0 + SW128((uint32_t)(r * 128 + c * 16)), src + r * 128 + c * 16);
        }
        CP_COMMIT();
    }

    float Ov[2][7][4] = {};
    float dden[2][2] = {};

    for (int t = 0; t < NT; t++) {
        if (t + 1 < NT) {
            const uint32_t kb = KB0 + (uint32_t)(((t + 1) & 1) * 16384);
            const char* src = (const char*)g_qk + (size_t)(half * 4608 + (t + 1) * 128) * 128;
            #pragma unroll
            for (int it = 0; it < 4; it++) {
                int idx = it * 256 + tid;
                int r = idx >> 3, c = idx & 7;
                CP_ASYNC16(kb + SW128((uint32_t)(r * 128 + c * 16)), src + r * 128 + c * 16);
            }
            CP_COMMIT();
            CP_WAIT1();
        } else {
            CP_WAIT0();
        }
        __syncthreads();

        const uint32_t KB = KB0 + (uint32_t)((t & 1) * 16384);

        // ---- S = Q K^T ----
        float Cs[2][8][4] = {};
        #pragma unroll
        for (int ks = 0; ks < 4; ks++) {
            uint32_t A0[4], A1[4];
            uint32_t ac = (uint32_t)(ks * 32 + ahi) ^ xm;
            LDSM_X4(A0[0], A0[1], A0[2], A0[3], QB + aoff + ac);
            LDSM_X4(A1[0], A1[1], A1[2], A1[3], QB + aoff + 2048 + ac);
            uint32_t bc = (uint32_t)(ks * 32 + bshi) ^ xm;
            #pragma unroll
            for (int np = 0; np < 4; np++) {
                uint32_t B[4];
                LDSM_X4(B[0], B[1], B[2], B[3], KB + bsb + (uint32_t)(np * 2048) + bc);
                MMA(Cs[0][2 * np],     A0[0], A0[1], A0[2], A0[3], B[0], B[1]);
                MMA(Cs[0][2 * np + 1], A0[0], A0[1], A0[2], A0[3], B[2], B[3]);
                MMA(Cs[1][2 * np],     A1[0], A1[1], A1[2], A1[3], B[0], B[1]);
                MMA(Cs[1][2 * np + 1], A1[0], A1[1], A1[2], A1[3], B[2], B[3]);
            }
        }

        // ---- P = exp2(S*log2e/49) via single-MUFU ex2.approx ----
        uint32_t aP[2][4][4];
        #pragma unroll
        for (int m = 0; m < 2; m++) {
            #pragma unroll
            for (int nt = 0; nt < 8; nt++) {
                float e0 = fast_ex2(Cs[m][nt][0] * CEXP);
                float e1 = fast_ex2(Cs[m][nt][1] * CEXP);
                float e2 = fast_ex2(Cs[m][nt][2] * CEXP);
                float e3 = fast_ex2(Cs[m][nt][3] * CEXP);
                dden[m][0] += e0 + e1;
                dden[m][1] += e2 + e3;
                int kk = nt >> 1;
                if ((nt & 1) == 0) {
                    aP[m][kk][0] = pack_bf16(e0, e1);
                    aP[m][kk][1] = pack_bf16(e2, e3);
                } else {
                    aP[m][kk][2] = pack_bf16(e0, e1);
                    aP[m][kk][3] = pack_bf16(e2, e3);
                }
            }
        }

        // ---- O += P V (cols 56..63 skipped) ----
        #pragma unroll
        for (int ks = 0; ks < 4; ks++) {
            #pragma unroll
            for (int dp = 0; dp < 4; dp++) {
                uint32_t B[4];
                LDSM_X4T(B[0], B[1], B[2], B[3],
                         KB + bvb + (uint32_t)(ks * 2048) +
                         (((uint32_t)(dp * 32 + bvhi)) ^ xm));
                MMA(Ov[0][2 * dp], aP[0][ks][0], aP[0][ks][1], aP[0][ks][2], aP[0][ks][3], B[0], B[1]);
                MMA(Ov[1][2 * dp], aP[1][ks][0], aP[1][ks][1], aP[1][ks][2], aP[1][ks][3], B[0], B[1]);
                if (dp < 3) {
                    MMA(Ov[0][2 * dp + 1], aP[0][ks][0], aP[0][ks][1], aP[0][ks][2], aP[0][ks][3], B[2], B[3]);
                    MMA(Ov[1][2 * dp + 1], aP[1][ks][0], aP[1][ks][1], aP[1][ks][2], aP[1][ks][3], B[2], B[3]);
                }
            }
        }
        __syncthreads();
    }

    const int part = half * 2 + wn;
    #pragma unroll
    for (int m = 0; m < 2; m++) {
        #pragma unroll
        for (int i = 0; i < 2; i++) {
            float v = dden[m][i];
            v += __shfl_xor_sync(0xFFFFFFFFu, v, 1);
            v += __shfl_xor_sync(0xFFFFFFFFu, v, 2);
            if (tig == 0)
                g_den[part * NR + q0 + wm * 32 + m * 16 + g + i * 8] = v;
        }
    }

    #pragma unroll
    for (int m = 0; m < 2; m++) {
        int r0 = q0 + wm * 32 + m * 16 + g;
        float* base = g_opart + ((size_t)part * NR + r0) * 64;
        #pragma unroll
        for (int nt = 0; nt < 7; nt++) {
            int col = nt * 8 + 2 * tig;
            *(float2*)(base + col)          = make_float2(Ov[m][nt][0], Ov[m][nt][1]);
            *(float2*)(base + 8 * 64 + col) = make_float2(Ov[m][nt][2], Ov[m][nt][3]);
        }
    }
}

// ---------------------------------------------------------------------------
// Kernel C: pw partial GEMM. Grid = 64 windows x 2 i-halves. Combines the
// 4 attention partials + normalization inline; 4o x 4p register tiles.
// ---------------------------------------------------------------------------
__global__ void __launch_bounds__(256) pw_part(const float* __restrict__ pww) {
    __shared__ float sh_y[72][52];
    __shared__ float sh_w[72][48];

    const int tid = threadIdx.x;
    const int win = blockIdx.x >> 1;
    const int ig  = blockIdx.x & 1;
    const int i0  = ig * 72;

    // load yhat chunk: combine 4 opart partials + normalize
    for (int idx = tid; idx < 72 * 13; idx += 256) {
        int i = idx / 13, q = idx - i * 13;
        int r = win * C3 + i0 + i;
        int base = r * 64 + 4 * q;
        float4 a = *(const float4*)(g_opart + base);
        float4 b = *(const float4*)(g_opart + NR * 64 + base);
        float4 c = *(const float4*)(g_opart + 2 * NR * 64 + base);
        float4 d = *(const float4*)(g_opart + 3 * NR * 64 + base);
        float rd = fast_rcp(g_den[r] + g_den[NR + r] + g_den[2 * NR + r] + g_den[3 * NR + r]);
        float4 o;
        o.x = (a.x + b.x + c.x + d.x) * rd;
        o.y = (a.y + b.y + c.y + d.y) * rd;
        o.z = (a.z + b.z + c.z + d.z) * rd;
        o.w = (a.w + b.w + c.w + d.w) * rd;
        *(float4*)&sh_y[i][4 * q] = o;
    }
    // weights transposed: sh_w[i][o]
    for (int idx = tid; idx < 72 * 48; idx += 256) {
        int i = idx / 48, o = idx - i * 48;
        sh_w[i][o] = pww[o * C3 + i0 + i];
    }
    __syncthreads();

    if (tid < 156) {                 // 12 o-tiles x 13 p-tiles
        const int ot = tid / 13, pg = tid - ot * 13;
        const int o0 = 4 * ot, p0 = 4 * pg;
        float acc[4][4] = {};
        #pragma unroll 8
        for (int i = 0; i < 72; i++) {
            float4 y = *(const float4*)&sh_y[i][p0];
            float4 w = *(const float4*)&sh_w[i][o0];
            acc[0][0] += w.x * y.x; acc[0][1] += w.x * y.y; acc[0][2] += w.x * y.z; acc[0][3] += w.x * y.w;
            acc[1][0] += w.y * y.x; acc[1][1] += w.y * y.y; acc[1][2] += w.y * y.z; acc[1][3] += w.y * y.w;
            acc[2][0] += w.z * y.x; acc[2][1] += w.z * y.y; acc[2][2] += w.z * y.z; acc[2][3] += w.z * y.w;
            acc[3][0] += w.w * y.x; acc[3][1] += w.w * y.y; acc[3][2] += w.w * y.z; acc[3][3] += w.w * y.w;
        }
        float* base = g_pwpart + ((size_t)(ig * 64 + win) * CC + o0) * 52 + p0;
        #pragma unroll
        for (int j = 0; j < 4; j++)
            *(float4*)(base + j * 52) =
                make_float4(acc[j][0], acc[j][1], acc[j][2], acc[j][3]);
    }
}

// ---------------------------------------------------------------------------
// Kernel D: final sum + bias + residual (elementwise over output).
// ---------------------------------------------------------------------------
__global__ void __launch_bounds__(256) pw_final(const float* __restrict__ x,
                                                const float* __restrict__ pb,
                                                float* __restrict__ out) {
    int idx = blockIdx.x * 256 + threadIdx.x;
    if (idx >= CC * HW) return;
    int o  = idx / HW;
    int hw = idx - o * HW;
    int h = hw / WW, w = hw - h * WW;
    int win = (h / 7) * 8 + (w / 7);
    int p   = (h % 7) * 7 + (w % 7);
    float v = g_pwpart[((size_t)win * CC + o) * 52 + p] +
              g_pwpart[((size_t)(64 + win) * CC + o) * 52 + p];
    out[idx] = x[idx] + pb[o] + v;
}

// ---------------------------------------------------------------------------
extern "C" void kernel_launch(void* const* d_in, const int* in_sizes, int n_in,
                              void* d_out, int out_size) {
    const float* x  = (const float*)d_in[0];
    const float* w3 = (const float*)d_in[1];
    const float* w5 = (const float*)d_in[2];
    const float* w7 = (const float*)d_in[3];
    const float* pw = (const float*)d_in[4];
    const float* pb = (const float*)d_in[5];
    float* out = (float*)d_out;

    cudaFuncSetAttribute(attn_kernel,
                         cudaFuncAttributeMaxDynamicSharedMemorySize, 49152);

    conv_kernel<<<384, 256>>>(x, w3, w5, w7);
    attn_kernel<<<144, 256, 49152>>>();
    pw_part<<<128, 256>>>(pw);
    pw_final<<<(CC * HW + 255) / 256, 256>>>(x, pb, out);
}

// round 6
// speedup vs baseline: 12.1093x; 1.0181x over previous
#include <cuda_runtime.h>
#include <cuda_fp16.h>
#include <stdint.h>

#define CC 48
#define C3 144
#define HH 56
#define WW 56
#define HW 3136
#define NR 9216
#define DD 49
#define NT 36                     // key tiles per half
#define CEXP 0.0294427559369f     // log2(e)/49

// ---------------- device scratch (allocation-free) ----------------
__device__ __half g_qk[NR * 64];             // yf f16 [row][64]; col 49 = 1.0, 50..63 = 0
__device__ float g_opart[4 * NR * 64];       // raw partial O (4 partials, den at col 49)
__device__ float g_pwpart[2 * 64 * CC * 52]; // pw partial sums [ig][win][o][52]

// ---------------- PTX helpers ----------------
__device__ __forceinline__ uint32_t smem_u32(const void* p) {
    uint32_t a;
    asm("{ .reg .u64 t; cvta.to.shared.u64 t, %1; cvt.u32.u64 %0, t; }"
        : "=r"(a) : "l"(p));
    return a;
}
#define SW128(o) ((o) ^ (((o) >> 3) & 0x70))

__device__ __forceinline__ float fast_rcp(float x) {
    float y;
    asm("rcp.approx.ftz.f32 %0, %1;" : "=f"(y) : "f"(x));
    return y;
}

// (c0, c1) -> f16x2 of exp2(c*CEXP); lo = c0 (k), hi = c1 (k+1)
__device__ __forceinline__ uint32_t exp_pair(float c0, float c1, uint32_t ch2) {
    uint32_t h;
    asm("cvt.rn.f16x2.f32 %0, %1, %2;" : "=r"(h) : "f"(c1), "f"(c0));
    asm("mul.f16x2 %0, %1, %2;" : "=r"(h) : "r"(h), "r"(ch2));
    asm("ex2.approx.f16x2 %0, %1;" : "=r"(h) : "r"(h));
    return h;
}

#define CP_ASYNC16(dst, src) \
    asm volatile("cp.async.cg.shared.global [%0], [%1], 16;" :: "r"(dst), "l"(src))
#define CP_COMMIT() asm volatile("cp.async.commit_group;" ::: "memory")
#define CP_WAIT0()  asm volatile("cp.async.wait_group 0;" ::: "memory")
#define CP_WAIT1()  asm volatile("cp.async.wait_group 1;" ::: "memory")

#define LDSM_X4(r0, r1, r2, r3, a) \
    asm volatile("ldmatrix.sync.aligned.m8n8.x4.shared.b16 {%0,%1,%2,%3}, [%4];" \
                 : "=r"(r0), "=r"(r1), "=r"(r2), "=r"(r3) : "r"(a))
#define LDSM_X4T(r0, r1, r2, r3, a) \
    asm volatile("ldmatrix.sync.aligned.m8n8.x4.trans.shared.b16 {%0,%1,%2,%3}, [%4];" \
                 : "=r"(r0), "=r"(r1), "=r"(r2), "=r"(r3) : "r"(a))

#define MMA(d, a0, a1, a2, a3, b0, b1) \
    asm volatile("mma.sync.aligned.m16n8k16.row.col.f32.f16.f16.f32 " \
                 "{%0,%1,%2,%3}, {%4,%5,%6,%7}, {%8,%9}, {%0,%1,%2,%3};" \
                 : "+f"((d)[0]), "+f"((d)[1]), "+f"((d)[2]), "+f"((d)[3]) \
                 : "r"(a0), "r"(a1), "r"(a2), "r"(a3), "r"(b0), "r"(b1))

// ---------------------------------------------------------------------------
// Kernel A: depthwise convs, smem-tiled. Grid = 48 channels x 8 row-strips.
// Writes f16 yf; col 49 = 1.0 (softmax-shift + denominator column).
// ---------------------------------------------------------------------------
__global__ void __launch_bounds__(256) conv_kernel(const float* __restrict__ x,
                                                   const float* __restrict__ w3,
                                                   const float* __restrict__ w5,
                                                   const float* __restrict__ w7) {
    __shared__ float xs[13][64];
    __shared__ float sw[83];

    const int tid = threadIdx.x;
    const int c   = blockIdx.x >> 3;
    const int h0  = (blockIdx.x & 7) * 7;

    for (int j = blockIdx.x * 256 + tid; j < NR * 15; j += 384 * 256) {
        int r = j / 15, cc = j - r * 15;
        g_qk[r * 64 + 49 + cc] = __float2half(cc == 0 ? 1.f : 0.f);
    }

    const float* xc = x + c * HW;
    for (int idx = tid; idx < 13 * 64; idx += 256) {
        int r = idx >> 6, wc = idx & 63;
        int hh = h0 - 3 + r, w = wc - 3;
        float v = 0.f;
        if (hh >= 0 && hh < HH && w >= 0 && w < WW) v = xc[hh * WW + w];
        xs[r][wc] = v;
    }
    if (tid < 83) {
        float v;
        if (tid < 9)       v = w3[c * 9 + tid];
        else if (tid < 34) v = w5[c * 25 + tid - 9];
        else               v = w7[c * 49 + tid - 34];
        sw[tid] = v;
    }
    __syncthreads();

    for (int idx = tid; idx < 3 * 7 * WW; idx += 256) {
        int b   = idx / 392;
        int rem = idx - b * 392;
        int ho  = rem / WW;
        int w   = rem - ho * WW;
        float sum = 0.f;
        if (b == 0) {
            const float* wp = sw;
            #pragma unroll
            for (int dh = 0; dh < 3; dh++)
                #pragma unroll
                for (int dw = 0; dw < 3; dw++)
                    sum += xs[ho + 2 + dh][w + 2 + dw] * wp[dh * 3 + dw];
        } else if (b == 1) {
            const float* wp = sw + 9;
            #pragma unroll
            for (int dh = 0; dh < 5; dh++)
                #pragma unroll
                for (int dw = 0; dw < 5; dw++)
                    sum += xs[ho + 1 + dh][w + 1 + dw] * wp[dh * 5 + dw];
        } else {
            const float* wp = sw + 34;
            #pragma unroll
            for (int dh = 0; dh < 7; dh++)
                #pragma unroll
                for (int dw = 0; dw < 7; dw++)
                    sum += xs[ho + dh][w + dw] * wp[dh * 7 + dw];
        }
        int h   = h0 + ho;
        int lin = h * WW + w;
        int g   = lin / DD;
        int p   = lin - g * DD;
        int c3  = b * CC + c;
        g_qk[(g * C3 + c3) * 64 + p] = __float2half(sum);
    }
}

// ---------------------------------------------------------------------------
// Kernel B: f16 HMMA flash attention. 8 warps = 4(m) x 2(n).
// S gets uniform +1 from the ones column (softmax-invariant); same column
// yields the denominator in O col 49. exp interleaved with PV MMAs.
// ---------------------------------------------------------------------------
__global__ void __launch_bounds__(256, 1) attn_kernel() {
    extern __shared__ char smraw[];
    const uint32_t SB  = smem_u32(smraw);
    const uint32_t QB  = SB;
    const uint32_t KB0 = SB + 16384;

    const int tid  = threadIdx.x;
    const int lane = tid & 31;
    const int wid  = tid >> 5;
    const int wm = wid >> 1, wn = wid & 1;
    const int g = lane >> 2, tig = lane & 3;
    const int bq = blockIdx.x >> 1, half = blockIdx.x & 1;
    const int q0 = bq * 128;

    uint32_t ch2;
    asm("{.reg .b16 h; cvt.rn.f16.f32 h, %1; mov.b32 %0, {h, h};}"
        : "=r"(ch2) : "f"(CEXP));

    const int l7 = lane & 7;
    const uint32_t xm   = (uint32_t)(l7 << 4);
    const uint32_t aoff = (uint32_t)((wm * 32 + l7 + ((lane & 8) ? 8 : 0)) * 128);
    const uint32_t ahi  = (lane & 16) ? 16u : 0u;
    const uint32_t bsb  = (uint32_t)((wn * 64 + l7 + ((lane & 16) ? 8 : 0)) * 128);
    const uint32_t bshi = (lane & 8) ? 16u : 0u;
    const uint32_t bvb  = (uint32_t)((wn * 64 + l7 + ((lane & 8) ? 8 : 0)) * 128);
    const uint32_t bvhi = (lane & 16) ? 16u : 0u;

    {
        const char* src = (const char*)g_qk + (size_t)q0 * 128;
        #pragma unroll
        for (int it = 0; it < 4; it++) {
            int idx = it * 256 + tid;
            int r = idx >> 3, c = idx & 7;
            CP_ASYNC16(QB + SW128((uint32_t)(r * 128 + c * 16)), src + r * 128 + c * 16);
        }
        CP_COMMIT();
    }
    {
        const char* src = (const char*)g_qk + (size_t)(half * 4608) * 128;
        #pragma unroll
        for (int it = 0; it < 4; it++) {
            int idx = it * 256 + tid;
            int r = idx >> 3, c = idx & 7;
            CP_ASYNC16(KB0 + SW128((uint32_t)(r * 128 + c * 16)), src + r * 128 + c * 16);
        }
        CP_COMMIT();
    }

    float Ov[2][7][4] = {};

    for (int t = 0; t < NT; t++) {
        if (t + 1 < NT) {
            const uint32_t kb = KB0 + (uint32_t)(((t + 1) & 1) * 16384);
            const char* src = (const char*)g_qk + (size_t)(half * 4608 + (t + 1) * 128) * 128;
            #pragma unroll
            for (int it = 0; it < 4; it++) {
                int idx = it * 256 + tid;
                int r = idx >> 3, c = idx & 7;
                CP_ASYNC16(kb + SW128((uint32_t)(r * 128 + c * 16)), src + r * 128 + c * 16);
            }
            CP_COMMIT();
            CP_WAIT1();
        } else {
            CP_WAIT0();
        }
        __syncthreads();

        const uint32_t KB = KB0 + (uint32_t)((t & 1) * 16384);

        // ---- S = Q K^T (+1 uniform shift from ones column) ----
        float Cs[2][8][4] = {};
        #pragma unroll
        for (int ks = 0; ks < 4; ks++) {
            uint32_t A0[4], A1[4];
            uint32_t ac = (uint32_t)(ks * 32 + ahi) ^ xm;
            LDSM_X4(A0[0], A0[1], A0[2], A0[3], QB + aoff + ac);
            LDSM_X4(A1[0], A1[1], A1[2], A1[3], QB + aoff + 2048 + ac);
            uint32_t bc = (uint32_t)(ks * 32 + bshi) ^ xm;
            #pragma unroll
            for (int np = 0; np < 4; np++) {
                uint32_t B[4];
                LDSM_X4(B[0], B[1], B[2], B[3], KB + bsb + (uint32_t)(np * 2048) + bc);
                MMA(Cs[0][2 * np],     A0[0], A0[1], A0[2], A0[3], B[0], B[1]);
                MMA(Cs[0][2 * np + 1], A0[0], A0[1], A0[2], A0[3], B[2], B[3]);
                MMA(Cs[1][2 * np],     A1[0], A1[1], A1[2], A1[3], B[0], B[1]);
                MMA(Cs[1][2 * np + 1], A1[0], A1[1], A1[2], A1[3], B[2], B[3]);
            }
        }

        // ---- interleaved: exp(ks) in f16x2 feeding PV MMAs of step ks ----
        #pragma unroll
        for (int ks = 0; ks < 4; ks++) {
            uint32_t aP[2][4];
            #pragma unroll
            for (int m = 0; m < 2; m++) {
                const float* ce = Cs[m][2 * ks];
                const float* co = Cs[m][2 * ks + 1];
                aP[m][0] = exp_pair(ce[0], ce[1], ch2);
                aP[m][1] = exp_pair(ce[2], ce[3], ch2);
                aP[m][2] = exp_pair(co[0], co[1], ch2);
                aP[m][3] = exp_pair(co[2], co[3], ch2);
            }
            #pragma unroll
            for (int dp = 0; dp < 4; dp++) {
                uint32_t B[4];
                LDSM_X4T(B[0], B[1], B[2], B[3],
                         KB + bvb + (uint32_t)(ks * 2048) +
                         (((uint32_t)(dp * 32 + bvhi)) ^ xm));
                MMA(Ov[0][2 * dp], aP[0][0], aP[0][1], aP[0][2], aP[0][3], B[0], B[1]);
                MMA(Ov[1][2 * dp], aP[1][0], aP[1][1], aP[1][2], aP[1][3], B[0], B[1]);
                if (dp < 3) {
                    MMA(Ov[0][2 * dp + 1], aP[0][0], aP[0][1], aP[0][2], aP[0][3], B[2], B[3]);
                    MMA(Ov[1][2 * dp + 1], aP[1][0], aP[1][1], aP[1][2], aP[1][3], B[2], B[3]);
                }
            }
        }
        __syncthreads();
    }

    // ---- store raw partial O (cols 0..55; den = col 49) ----
    const int part = half * 2 + wn;
    #pragma unroll
    for (int m = 0; m < 2; m++) {
        int r0 = q0 + wm * 32 + m * 16 + g;
        float* base = g_opart + ((size_t)part * NR + r0) * 64;
        #pragma unroll
        for (int nt = 0; nt < 7; nt++) {
            int col = nt * 8 + 2 * tig;
            *(float2*)(base + col)          = make_float2(Ov[m][nt][0], Ov[m][nt][1]);
            *(float2*)(base + 8 * 64 + col) = make_float2(Ov[m][nt][2], Ov[m][nt][3]);
        }
    }
}

// ---------------------------------------------------------------------------
// Kernel C: pw partial GEMM. Grid = 64 windows x 2 i-halves. Combines the
// 4 attention partials, normalizes by O col 49; 4o x 4p register tiles.
// ---------------------------------------------------------------------------
__global__ void __launch_bounds__(256) pw_part(const float* __restrict__ pww) {
    __shared__ float sh_y[72][52];
    __shared__ float sh_w[72][48];
    __shared__ float sh_rd[72];

    const int tid = threadIdx.x;
    const int win = blockIdx.x >> 1;
    const int ig  = blockIdx.x & 1;
    const int i0  = ig * 72;

    if (tid < 72) {
        int r = win * C3 + i0 + tid;
        float den = g_opart[r * 64 + 49] + g_opart[NR * 64 + r * 64 + 49] +
                    g_opart[2 * NR * 64 + r * 64 + 49] + g_opart[3 * NR * 64 + r * 64 + 49];
        sh_rd[tid] = fast_rcp(den);
    }
    __syncthreads();

    for (int idx = tid; idx < 72 * 13; idx += 256) {
        int i = idx / 13, q = idx - i * 13;
        int r = win * C3 + i0 + i;
        int base = r * 64 + 4 * q;
        float4 a = *(const float4*)(g_opart + base);
        float4 b = *(const float4*)(g_opart + NR * 64 + base);
        float4 c = *(const float4*)(g_opart + 2 * NR * 64 + base);
        float4 d = *(const float4*)(g_opart + 3 * NR * 64 + base);
        float rd = sh_rd[i];
        float4 o;
        o.x = (a.x + b.x + c.x + d.x) * rd;
        o.y = (a.y + b.y + c.y + d.y) * rd;
        o.z = (a.z + b.z + c.z + d.z) * rd;
        o.w = (a.w + b.w + c.w + d.w) * rd;
        *(float4*)&sh_y[i][4 * q] = o;
    }
    for (int idx = tid; idx < 72 * 48; idx += 256) {
        int i = idx / 48, o = idx - i * 48;
        sh_w[i][o] = pww[o * C3 + i0 + i];
    }
    __syncthreads();

    if (tid < 156) {                 // 12 o-tiles x 13 p-tiles
        const int ot = tid / 13, pg = tid - ot * 13;
        const int o0 = 4 * ot, p0 = 4 * pg;
        float acc[4][4] = {};
        #pragma unroll 8
        for (int i = 0; i < 72; i++) {
            float4 y = *(const float4*)&sh_y[i][p0];
            float4 w = *(const float4*)&sh_w[i][o0];
            acc[0][0] += w.x * y.x; acc[0][1] += w.x * y.y; acc[0][2] += w.x * y.z; acc[0][3] += w.x * y.w;
            acc[1][0] += w.y * y.x; acc[1][1] += w.y * y.y; acc[1][2] += w.y * y.z; acc[1][3] += w.y * y.w;
            acc[2][0] += w.z * y.x; acc[2][1] += w.z * y.y; acc[2][2] += w.z * y.z; acc[2][3] += w.z * y.w;
            acc[3][0] += w.w * y.x; acc[3][1] += w.w * y.y; acc[3][2] += w.w * y.z; acc[3][3] += w.w * y.w;
        }
        float* base = g_pwpart + ((size_t)(ig * 64 + win) * CC + o0) * 52 + p0;
        #pragma unroll
        for (int j = 0; j < 4; j++)
            *(float4*)(base + j * 52) =
                make_float4(acc[j][0], acc[j][1], acc[j][2], acc[j][3]);
    }
}

// ---------------------------------------------------------------------------
// Kernel D: final sum + bias + residual.
// ---------------------------------------------------------------------------
__global__ void __launch_bounds__(256) pw_final(const float* __restrict__ x,
                                                const float* __restrict__ pb,
                                                float* __restrict__ out) {
    int idx = blockIdx.x * 256 + threadIdx.x;
    if (idx >= CC * HW) return;
    int o  = idx / HW;
    int hw = idx - o * HW;
    int h = hw / WW, w = hw - h * WW;
    int win = (h / 7) * 8 + (w / 7);
    int p   = (h % 7) * 7 + (w % 7);
    float v = g_pwpart[((size_t)win * CC + o) * 52 + p] +
              g_pwpart[((size_t)(64 + win) * CC + o) * 52 + p];
    out[idx] = x[idx] + pb[o] + v;
}

// ---------------------------------------------------------------------------
extern "C" void kernel_launch(void* const* d_in, const int* in_sizes, int n_in,
                              void* d_out, int out_size) {
    const float* x  = (const float*)d_in[0];
    const float* w3 = (const float*)d_in[1];
    const float* w5 = (const float*)d_in[2];
    const float* w7 = (const float*)d_in[3];
    const float* pw = (const float*)d_in[4];
    const float* pb = (const float*)d_in[5];
    float* out = (float*)d_out;

    cudaFuncSetAttribute(attn_kernel,
                         cudaFuncAttributeMaxDynamicSharedMemorySize, 49152);

    conv_kernel<<<384, 256>>>(x, w3, w5, w7);
    attn_kernel<<<144, 256, 49152>>>();
    pw_part<<<128, 256>>>(pw);
    pw_final<<<(CC * HW + 255) / 256, 256>>>(x, pb, out);
}